// round 12
// baseline (speedup 1.0000x reference)
#include <cuda_runtime.h>
#include <cfloat>
#include <cstdint>

// Problem constants
#define NF   128      // features
#define NCL  64       // clusters
#define TN   128      // tokens per CTA
#define KC   16       // features staged per iteration
#define CST  132      // centers smem row stride (floats) -> conflict-free
#define XST  132      // x-tile smem row stride (floats)
#define MAXC 16384    // max CTAs of kernel1 supported by scratch

typedef unsigned long long ull;

// Global scratch for per-CTA partial argmins (static device arrays: no allocation)
__device__ float g_pval[NCL * MAXC];
__device__ int   g_pidx[NCL * MAXC];

__device__ __forceinline__ ull fma2(ull a, ull b, ull c) {
    ull d;
    asm("fma.rn.f32x2 %0, %1, %2, %3;" : "=l"(d) : "l"(a), "l"(b), "l"(c));
    return d;
}
__device__ __forceinline__ ull dup2(float v) {
    ull d; unsigned u = __float_as_uint(v);
    asm("mov.b64 %0, {%1, %1};" : "=l"(d) : "r"(u));
    return d;
}
__device__ __forceinline__ float2 unpk(ull v) {
    float2 f;
    f.x = __uint_as_float((unsigned)(v & 0xFFFFFFFFu));
    f.y = __uint_as_float((unsigned)(v >> 32));
    return f;
}

// Kernel 1: fused (x . c) GEMM + x2 + per-CTA argmin over 128 tokens x 64 clusters.
// 128 threads; thread microtile = 8 tokens (as 4 f32x2 pairs) x 8 clusters.
__global__ void __launch_bounds__(128, 3)
cluster_argmin_kernel(const float* __restrict__ x,
                      const float* __restrict__ cc,
                      int N)
{
    __shared__ __align__(16) float cs[NCL * CST];   // centers, padded rows
    __shared__ __align__(16) float xs[KC * XST];    // transposed x tile [feat][token]
    __shared__ float c2s[NCL];

    const int tid  = threadIdx.x;
    const int tx   = tid & 7;    // cluster group: clusters tx + 8*c
    const int ty   = tid >> 3;   // token group:  tokens  ty*8 + 0..7
    const int base = blockIdx.x * TN;

    // Stage centers: 64x128 floats = 2048 float4; 128 threads -> 16 each (coalesced)
    #pragma unroll
    for (int r = 0; r < 16; ++r) {
        int idx = r * 128 + tid;          // float4 index 0..2047
        int k   = idx >> 5;               // 32 float4 per center row
        int f4  = idx & 31;
        float4 v = reinterpret_cast<const float4*>(cc)[idx];
        *reinterpret_cast<float4*>(&cs[k * CST + f4 * 4]) = v;
    }
    __syncthreads();

    // c2 per cluster (one-time, cheap)
    if (tid < NCL) {
        const float* row = &cs[tid * CST];
        float s = 0.f;
        #pragma unroll 8
        for (int j = 0; j < NF; ++j) s = fmaf(row[j], row[j], s);
        c2s[tid] = s;
    }

    // Accumulators: xc for [token-pair p][cluster c], and x2 per token-pair
    ull acc[4][8];
    ull x2a[4];
    #pragma unroll
    for (int p = 0; p < 4; ++p) {
        x2a[p] = 0ull;
        #pragma unroll
        for (int c = 0; c < 8; ++c) acc[p][c] = 0ull;
    }

    // Main loop over feature stages
    for (int s = 0; s < NF / KC; ++s) {
        __syncthreads();   // protect xs from previous stage readers
        // Stage x tile transposed: 128 tokens x 16 feats = 512 float4; 4 per thread
        #pragma unroll
        for (int r = 0; r < 4; ++r) {
            int idx = r * 128 + tid;      // 0..511
            int t   = idx >> 2;           // token local 0..127 (KC/4 = 4 f4 per token)
            int f4  = idx & 3;
            int gt  = base + t;
            float4 v = make_float4(0.f, 0.f, 0.f, 0.f);
            if (gt < N)
                v = *reinterpret_cast<const float4*>(&x[(size_t)gt * NF + s * KC + f4 * 4]);
            xs[(f4 * 4 + 0) * XST + t] = v.x;
            xs[(f4 * 4 + 1) * XST + t] = v.y;
            xs[(f4 * 4 + 2) * XST + t] = v.z;
            xs[(f4 * 4 + 3) * XST + t] = v.w;
        }
        __syncthreads();

        #pragma unroll
        for (int j4 = 0; j4 < KC / 4; ++j4) {
            // 8 clusters' center values for 4 features (conflict-free: stride 132)
            float4 bq[8];
            #pragma unroll
            for (int c = 0; c < 8; ++c)
                bq[c] = *reinterpret_cast<const float4*>(
                            &cs[(tx + 8 * c) * CST + s * KC + j4 * 4]);
            #pragma unroll
            for (int u = 0; u < 4; ++u) {
                const float* xrow = &xs[(j4 * 4 + u) * XST + ty * 8];
                ulonglong2 A01 = *reinterpret_cast<const ulonglong2*>(xrow);
                ulonglong2 A23 = *reinterpret_cast<const ulonglong2*>(xrow + 4);
                ull a[4] = {A01.x, A01.y, A23.x, A23.y};
                #pragma unroll
                for (int p = 0; p < 4; ++p) x2a[p] = fma2(a[p], a[p], x2a[p]);
                #pragma unroll
                for (int c = 0; c < 8; ++c) {
                    float bu = (u == 0) ? bq[c].x : (u == 1) ? bq[c].y
                             : (u == 2) ? bq[c].z : bq[c].w;
                    ull bb = dup2(bu);
                    #pragma unroll
                    for (int p = 0; p < 4; ++p)
                        acc[p][c] = fma2(a[p], bb, acc[p][c]);
                }
            }
        }
    }

    // Epilogue: per-thread argmin over its 8 tokens for each of its 8 clusters
    float bestv[8]; int besti[8];
    #pragma unroll
    for (int c = 0; c < 8; ++c) { bestv[c] = FLT_MAX; besti[c] = 0x7FFFFFFF; }

    #pragma unroll
    for (int p = 0; p < 4; ++p) {
        float2 xx = unpk(x2a[p]);
        int g0 = base + ty * 8 + 2 * p;
        int g1 = g0 + 1;
        #pragma unroll
        for (int c = 0; c < 8; ++c) {
            int k = tx + 8 * c;
            float c2 = c2s[k];
            float2 xc = unpk(acc[p][c]);
            float s0 = (xx.x + c2) - 2.0f * xc.x;
            float s1 = (xx.y + c2) - 2.0f * xc.y;
            if (g0 < N && (s0 < bestv[c] || (s0 == bestv[c] && g0 < besti[c]))) {
                bestv[c] = s0; besti[c] = g0;
            }
            if (g1 < N && (s1 < bestv[c] || (s1 == bestv[c] && g1 < besti[c]))) {
                bestv[c] = s1; besti[c] = g1;
            }
        }
    }

    // Cross-thread reduction within CTA (reuse xs storage)
    __syncthreads();
    float* redv = xs;                                   // 64*16 floats
    int*   redi = reinterpret_cast<int*>(xs + NCL * 16);
    #pragma unroll
    for (int c = 0; c < 8; ++c) {
        int k = tx + 8 * c;
        redv[k * 16 + ty] = bestv[c];
        redi[k * 16 + ty] = besti[c];
    }
    __syncthreads();
    if (tid < NCL) {
        float bv = FLT_MAX; int bi = 0x7FFFFFFF;
        #pragma unroll
        for (int t = 0; t < 16; ++t) {
            float v = redv[tid * 16 + t];
            int   i = redi[tid * 16 + t];
            if (v < bv || (v == bv && i < bi)) { bv = v; bi = i; }
        }
        g_pval[tid * MAXC + blockIdx.x] = bv;
        g_pidx[tid * MAXC + blockIdx.x] = bi;
    }
}

// Kernel 2: reduce partials per cluster and gather winning token's row.
__global__ void reduce_gather_kernel(const float* __restrict__ x, int N,
                                     int nParts, float* __restrict__ out)
{
    __shared__ float sv[256];
    __shared__ int   si[256];
    const int k   = blockIdx.x;    // cluster
    const int tid = threadIdx.x;

    float bv = FLT_MAX; int bi = 0x7FFFFFFF;
    for (int i = tid; i < nParts; i += 256) {
        float v = g_pval[k * MAXC + i];
        int  ix = g_pidx[k * MAXC + i];
        if (v < bv || (v == bv && ix < bi)) { bv = v; bi = ix; }
    }
    sv[tid] = bv; si[tid] = bi;
    __syncthreads();
    #pragma unroll
    for (int off = 128; off > 0; off >>= 1) {
        if (tid < off) {
            float v = sv[tid + off]; int ix = si[tid + off];
            if (v < sv[tid] || (v == sv[tid] && ix < si[tid])) {
                sv[tid] = v; si[tid] = ix;
            }
        }
        __syncthreads();
    }
    int bidx = si[0];
    if (tid < NF)
        out[k * NF + tid] = x[(size_t)bidx * NF + tid];
}

extern "C" void kernel_launch(void* const* d_in, const int* in_sizes, int n_in,
                              void* d_out, int out_size)
{
    const float* x  = (const float*)d_in[0];   // (1, N, 128) fp32
    const float* cc = (const float*)d_in[1];   // (64, 128) fp32
    float* out = (float*)d_out;                // (1, 64, 128) fp32

    int N    = in_sizes[0] / NF;
    int grid = (N + TN - 1) / TN;              // 7813 for N = 1e6 (fits MAXC)

    cluster_argmin_kernel<<<grid, 128>>>(x, cc, N);
    reduce_gather_kernel<<<NCL, 256>>>(x, N, grid, out);
}

// round 13
// speedup vs baseline: 1.0032x; 1.0032x over previous
#include <cuda_runtime.h>
#include <cfloat>
#include <cstdint>

// Problem constants
#define NF   128      // features
#define NCL  64       // clusters
#define TN   128      // tokens per CTA
#define KC   16       // features staged per iteration
#define CST  132      // centers smem row stride (floats) -> conflict-free
#define XST  132      // x-tile smem row stride (floats)
#define MAXC 16384    // max CTAs of kernel1 supported by scratch

typedef unsigned long long ull;

// Global scratch for per-CTA partial argmins (static device arrays: no allocation)
__device__ float g_pval[NCL * MAXC];
__device__ int   g_pidx[NCL * MAXC];

__device__ __forceinline__ ull fma2(ull a, ull b, ull c) {
    ull d;
    asm("fma.rn.f32x2 %0, %1, %2, %3;" : "=l"(d) : "l"(a), "l"(b), "l"(c));
    return d;
}
__device__ __forceinline__ ull dup2(float v) {
    ull d; unsigned u = __float_as_uint(v);
    asm("mov.b64 %0, {%1, %1};" : "=l"(d) : "r"(u));
    return d;
}
__device__ __forceinline__ float2 unpk(ull v) {
    float2 f;
    f.x = __uint_as_float((unsigned)(v & 0xFFFFFFFFu));
    f.y = __uint_as_float((unsigned)(v >> 32));
    return f;
}

// Kernel 1: fused (x . c) GEMM + x2 + per-CTA argmin over 128 tokens x 64 clusters.
// 128 threads; thread microtile = 8 tokens (as 4 f32x2 pairs) x 8 clusters.
__global__ void __launch_bounds__(128, 3)
cluster_argmin_kernel(const float* __restrict__ x,
                      const float* __restrict__ cc,
                      int N)
{
    __shared__ __align__(16) float cs[NCL * CST];   // centers, padded rows
    __shared__ __align__(16) float xs[KC * XST];    // transposed x tile [feat][token]
    __shared__ float c2s[NCL];

    const int tid  = threadIdx.x;
    const int tx   = tid & 7;    // cluster group: clusters tx + 8*c
    const int ty   = tid >> 3;   // token group:  tokens  ty*8 + 0..7
    const int base = blockIdx.x * TN;

    // Stage centers: 64x128 floats = 2048 float4; 128 threads -> 16 each (coalesced)
    #pragma unroll
    for (int r = 0; r < 16; ++r) {
        int idx = r * 128 + tid;          // float4 index 0..2047
        int k   = idx >> 5;               // 32 float4 per center row
        int f4  = idx & 31;
        float4 v = reinterpret_cast<const float4*>(cc)[idx];
        *reinterpret_cast<float4*>(&cs[k * CST + f4 * 4]) = v;
    }
    __syncthreads();

    // c2 per cluster (one-time, cheap)
    if (tid < NCL) {
        const float* row = &cs[tid * CST];
        float s = 0.f;
        #pragma unroll 8
        for (int j = 0; j < NF; ++j) s = fmaf(row[j], row[j], s);
        c2s[tid] = s;
    }

    // Accumulators: xc for [token-pair p][cluster c], and x2 per token-pair
    ull acc[4][8];
    ull x2a[4];
    #pragma unroll
    for (int p = 0; p < 4; ++p) {
        x2a[p] = 0ull;
        #pragma unroll
        for (int c = 0; c < 8; ++c) acc[p][c] = 0ull;
    }

    // Main loop over feature stages
    for (int s = 0; s < NF / KC; ++s) {
        __syncthreads();   // protect xs from previous stage readers
        // Stage x tile transposed: 128 tokens x 16 feats = 512 float4; 4 per thread
        #pragma unroll
        for (int r = 0; r < 4; ++r) {
            int idx = r * 128 + tid;      // 0..511
            int t   = idx >> 2;           // token local 0..127 (KC/4 = 4 f4 per token)
            int f4  = idx & 3;
            int gt  = base + t;
            float4 v = make_float4(0.f, 0.f, 0.f, 0.f);
            if (gt < N)
                v = *reinterpret_cast<const float4*>(&x[(size_t)gt * NF + s * KC + f4 * 4]);
            xs[(f4 * 4 + 0) * XST + t] = v.x;
            xs[(f4 * 4 + 1) * XST + t] = v.y;
            xs[(f4 * 4 + 2) * XST + t] = v.z;
            xs[(f4 * 4 + 3) * XST + t] = v.w;
        }
        __syncthreads();

        #pragma unroll
        for (int j4 = 0; j4 < KC / 4; ++j4) {
            // 8 clusters' center values for 4 features (conflict-free: stride 132)
            float4 bq[8];
            #pragma unroll
            for (int c = 0; c < 8; ++c)
                bq[c] = *reinterpret_cast<const float4*>(
                            &cs[(tx + 8 * c) * CST + s * KC + j4 * 4]);
            #pragma unroll
            for (int u = 0; u < 4; ++u) {
                const float* xrow = &xs[(j4 * 4 + u) * XST + ty * 8];
                ulonglong2 A01 = *reinterpret_cast<const ulonglong2*>(xrow);
                ulonglong2 A23 = *reinterpret_cast<const ulonglong2*>(xrow + 4);
                ull a[4] = {A01.x, A01.y, A23.x, A23.y};
                #pragma unroll
                for (int p = 0; p < 4; ++p) x2a[p] = fma2(a[p], a[p], x2a[p]);
                #pragma unroll
                for (int c = 0; c < 8; ++c) {
                    float bu = (u == 0) ? bq[c].x : (u == 1) ? bq[c].y
                             : (u == 2) ? bq[c].z : bq[c].w;
                    ull bb = dup2(bu);
                    #pragma unroll
                    for (int p = 0; p < 4; ++p)
                        acc[p][c] = fma2(a[p], bb, acc[p][c]);
                }
            }
        }
    }

    // Epilogue: per-thread argmin over its 8 tokens for each of its 8 clusters
    float bestv[8]; int besti[8];
    #pragma unroll
    for (int c = 0; c < 8; ++c) { bestv[c] = FLT_MAX; besti[c] = 0x7FFFFFFF; }

    #pragma unroll
    for (int p = 0; p < 4; ++p) {
        float2 xx = unpk(x2a[p]);
        int g0 = base + ty * 8 + 2 * p;
        int g1 = g0 + 1;
        #pragma unroll
        for (int c = 0; c < 8; ++c) {
            int k = tx + 8 * c;
            float c2 = c2s[k];
            float2 xc = unpk(acc[p][c]);
            float s0 = (xx.x + c2) - 2.0f * xc.x;
            float s1 = (xx.y + c2) - 2.0f * xc.y;
            if (g0 < N && (s0 < bestv[c] || (s0 == bestv[c] && g0 < besti[c]))) {
                bestv[c] = s0; besti[c] = g0;
            }
            if (g1 < N && (s1 < bestv[c] || (s1 == bestv[c] && g1 < besti[c]))) {
                bestv[c] = s1; besti[c] = g1;
            }
        }
    }

    // Cross-thread reduction within CTA (reuse xs storage)
    __syncthreads();
    float* redv = xs;                                   // 64*16 floats
    int*   redi = reinterpret_cast<int*>(xs + NCL * 16);
    #pragma unroll
    for (int c = 0; c < 8; ++c) {
        int k = tx + 8 * c;
        redv[k * 16 + ty] = bestv[c];
        redi[k * 16 + ty] = besti[c];
    }
    __syncthreads();
    if (tid < NCL) {
        float bv = FLT_MAX; int bi = 0x7FFFFFFF;
        #pragma unroll
        for (int t = 0; t < 16; ++t) {
            float v = redv[tid * 16 + t];
            int   i = redi[tid * 16 + t];
            if (v < bv || (v == bv && i < bi)) { bv = v; bi = i; }
        }
        g_pval[tid * MAXC + blockIdx.x] = bv;
        g_pidx[tid * MAXC + blockIdx.x] = bi;
    }
}

// Kernel 2: reduce partials per cluster and gather winning token's row.
__global__ void reduce_gather_kernel(const float* __restrict__ x, int N,
                                     int nParts, float* __restrict__ out)
{
    __shared__ float sv[256];
    __shared__ int   si[256];
    const int k   = blockIdx.x;    // cluster
    const int tid = threadIdx.x;

    float bv = FLT_MAX; int bi = 0x7FFFFFFF;
    for (int i = tid; i < nParts; i += 256) {
        float v = g_pval[k * MAXC + i];
        int  ix = g_pidx[k * MAXC + i];
        if (v < bv || (v == bv && ix < bi)) { bv = v; bi = ix; }
    }
    sv[tid] = bv; si[tid] = bi;
    __syncthreads();
    #pragma unroll
    for (int off = 128; off > 0; off >>= 1) {
        if (tid < off) {
            float v = sv[tid + off]; int ix = si[tid + off];
            if (v < sv[tid] || (v == sv[tid] && ix < si[tid])) {
                sv[tid] = v; si[tid] = ix;
            }
        }
        __syncthreads();
    }
    int bidx = si[0];
    if (tid < NF)
        out[k * NF + tid] = x[(size_t)bidx * NF + tid];
}

extern "C" void kernel_launch(void* const* d_in, const int* in_sizes, int n_in,
                              void* d_out, int out_size)
{
    const float* x  = (const float*)d_in[0];   // (1, N, 128) fp32
    const float* cc = (const float*)d_in[1];   // (64, 128) fp32
    float* out = (float*)d_out;                // (1, 64, 128) fp32

    int N    = in_sizes[0] / NF;
    int grid = (N + TN - 1) / TN;              // 7813 for N = 1e6 (fits MAXC)

    cluster_argmin_kernel<<<grid, 128>>>(x, cc, N);
    reduce_gather_kernel<<<NCL, 256>>>(x, N, grid, out);
}